// round 8
// baseline (speedup 1.0000x reference)
#include <cuda_runtime.h>
#include <math.h>

#define NB 16
#define PP 1024
#define CAP 224
#define TSEL 0.07f

static constexpr float KLOG  = 1442.6950408889634f;   // 1/(EPS*ln2)
static constexpr float NKLOG = -1442.6950408889634f;
static constexpr float LGEPS = 1e-8f;

// Persistent scratch (module globals; no runtime allocation)
__device__ float g_uK[NB * PP];
__device__ float g_vK[NB * PP];
__device__ float g_logmu2[NB * PP];
__device__ float g_lognu2[NB * PP];
__device__ float g_cmin[NB * PP];
__device__ float g_cminK[NB * PP];
__device__ float g_rmin[NB * PP];
__device__ float g_rminK[NB * PP];
__device__ float g_ct[CAP * NB * PP];             // (mn - C)*K, e-major
__device__ unsigned short g_cidx[CAP * NB * PP];  // row index
__device__ int   g_ccnt[NB * PP];
__device__ float g_rt[CAP * NB * PP];
__device__ unsigned short g_ridx[CAP * NB * PP];  // col index
__device__ int   g_rcnt[NB * PP];
__device__ float g_part[NB * 64];
__device__ float g_cost[NB];

__device__ __forceinline__ float ex2f(float x) {
    float y; asm("ex2.approx.ftz.f32 %0, %1;" : "=f"(y) : "f"(x)); return y;
}
__device__ __forceinline__ float lg2f(float x) {
    float y; asm("lg2.approx.ftz.f32 %0, %1;" : "=f"(y) : "f"(x)); return y;
}

__global__ void __launch_bounds__(256) init_k(const float* __restrict__ mu,
                                              const float* __restrict__ nu) {
    int t = blockIdx.x * blockDim.x + threadIdx.x;
    if (t < NB * PP) {
        g_logmu2[t] = log2f(mu[t] + LGEPS);
        g_lognu2[t] = log2f(nu[t] + LGEPS);
        g_uK[t] = KLOG;   // u = 1
    }
}

// ------------------------- setup: per-column min -------------------------
// grid (16,16): 64 cols/block over all 1024 rows.
__global__ void __launch_bounds__(256) colmin_k(const float* __restrict__ C) {
    const int n = blockIdx.y, cb = blockIdx.x;
    __shared__ float pm[16 * 64];
    const int tid = threadIdx.x;
    const int cg = tid & 15, rg = tid >> 4;
    const float4* Cp = (const float4*)(C + ((size_t)n << 20)
                       + (size_t)(rg * 64) * PP) + cb * 16 + cg;
    float4 mn = make_float4(1e30f, 1e30f, 1e30f, 1e30f);
#pragma unroll 8
    for (int r = 0; r < 64; ++r) {
        float4 c = Cp[r * (PP / 4)];
        mn.x = fminf(mn.x, c.x); mn.y = fminf(mn.y, c.y);
        mn.z = fminf(mn.z, c.z); mn.w = fminf(mn.w, c.w);
    }
    *(float4*)(pm + rg * 64 + cg * 4) = mn;
    __syncthreads();
    if (tid < 64) {
        float m = pm[tid];
#pragma unroll
        for (int k = 1; k < 16; ++k) m = fminf(m, pm[k * 64 + tid]);
        g_cmin[n * PP + cb * 64 + tid]  = m;
        g_cminK[n * PP + cb * 64 + tid] = KLOG * m;
    }
}

// ------------------------- setup: per-row min ----------------------------
// grid (16,16): 64 rows/block; warp handles 8 rows, one row at a time.
__global__ void __launch_bounds__(256) rowmin_k(const float* __restrict__ C) {
    const int n = blockIdx.y, rb = blockIdx.x;
    const int tid = threadIdx.x, w = tid >> 5, l = tid & 31;
    for (int r = 0; r < 8; ++r) {
        const int i = rb * 64 + w * 8 + r;
        const float4* Cp = (const float4*)(C + ((size_t)n << 20) + (size_t)i * PP);
        float m = 1e30f;
#pragma unroll
        for (int k = 0; k < 8; ++k) {
            float4 c = Cp[l + 32 * k];
            m = fminf(m, fminf(fminf(c.x, c.y), fminf(c.z, c.w)));
        }
#pragma unroll
        for (int o = 16; o; o >>= 1) m = fminf(m, __shfl_xor_sync(0xFFFFFFFFu, m, o));
        if (l == 0) { g_rmin[n * PP + i] = m; g_rminK[n * PP + i] = KLOG * m; }
    }
}

// --------------------- setup: column compaction --------------------------
// grid (4,16): warp owns 32 columns (lane = column), serial over rows ->
// deterministic ascending-row order, coalesced reads.
__global__ void __launch_bounds__(256) colcompact_k(const float* __restrict__ C) {
    const int n = blockIdx.y;
    const int tid = threadIdx.x, w = tid >> 5, l = tid & 31;
    const int j = blockIdx.x * 256 + w * 32 + l;
    const float mn = g_cmin[n * PP + j];
    const float th = mn + TSEL;
    const float* Cc = C + ((size_t)n << 20) + j;
    int cnt = 0;
    for (int r = 0; r < PP; ++r) {
        float c = Cc[(size_t)r * PP];
        if (c < th && cnt < CAP) {
            g_ct[(cnt * NB + n) * PP + j]   = (mn - c) * KLOG;
            g_cidx[(cnt * NB + n) * PP + j] = (unsigned short)r;
            cnt++;
        }
    }
    g_ccnt[n * PP + j] = cnt;
    for (int e = cnt; e < CAP; ++e) {
        g_ct[(e * NB + n) * PP + j]   = -1e9f;
        g_cidx[(e * NB + n) * PP + j] = 0;
    }
}

// ----------------------- setup: row compaction ---------------------------
// grid (128,16): warp per row; ballot-compaction preserves ascending col order.
__global__ void __launch_bounds__(256) rowcompact_k(const float* __restrict__ C) {
    const int n = blockIdx.y;
    const int tid = threadIdx.x, w = tid >> 5, l = tid & 31;
    const int i = blockIdx.x * 8 + w;
    const float mn = g_rmin[n * PP + i];
    const float th = mn + TSEL;
    const float* Cr = C + ((size_t)n << 20) + (size_t)i * PP;
    int base = 0;
    for (int cb = 0; cb < 32; ++cb) {
        float c = Cr[cb * 32 + l];
        bool p = c < th;
        unsigned msk = __ballot_sync(0xFFFFFFFFu, p);
        int e = base + __popc(msk & ((1u << l) - 1u));
        if (p && e < CAP) {
            g_rt[(e * NB + n) * PP + i]   = (mn - c) * KLOG;
            g_ridx[(e * NB + n) * PP + i] = (unsigned short)(cb * 32 + l);
        }
        base += __popc(msk);
    }
    if (base > CAP) base = CAP;
    if (l == 0) g_rcnt[n * PP + i] = base;
    for (int e = base + l; e < CAP; e += 32) {
        g_rt[(e * NB + n) * PP + i]   = -1e9f;
        g_ridx[(e * NB + n) * PP + i] = 0;
    }
}

// ------------------------ iteration: v update ----------------------------
// grid (8,16), 128 threads; thread = one column. Sparse sum with block offset.
__global__ void __launch_bounds__(128) colsweep_k() {
    const int n = blockIdx.y, jb = blockIdx.x;
    __shared__ float us[PP];
    __shared__ float red[128];
    const int tid = threadIdx.x;

    float lmax = -1e30f;
    const float4* up = (const float4*)(g_uK + n * PP);
    float4* us4 = (float4*)us;
#pragma unroll
    for (int k = tid; k < PP / 4; k += 128) {
        float4 u = up[k];
        us4[k] = u;
        lmax = fmaxf(lmax, fmaxf(fmaxf(u.x, u.y), fmaxf(u.z, u.w)));
    }
    red[tid] = lmax;
    __syncthreads();
#pragma unroll
    for (int st = 64; st; st >>= 1) {
        if (tid < st) red[tid] = fmaxf(red[tid], red[tid + st]);
        __syncthreads();
    }
    const float Bu = red[0];
#pragma unroll
    for (int k = tid; k < PP; k += 128) us[k] -= Bu;
    __syncthreads();

    const int j = jb * 128 + tid;
    int cnt = g_ccnt[n * PP + j];
#pragma unroll
    for (int o = 16; o; o >>= 1) cnt = max(cnt, __shfl_xor_sync(0xFFFFFFFFu, cnt, o));

    const float* tp = g_ct + n * PP + j;
    const unsigned short* ip = g_cidx + n * PP + j;
    float s = 0.f;
#pragma unroll 4
    for (int e = 0; e < cnt; ++e) {
        float t  = tp[e * (NB * PP)];
        int idx  = ip[e * (NB * PP)];
        s += ex2f(us[idx] + t);
    }
    float lse = Bu - g_cminK[n * PP + j] + lg2f(s);
    g_vK[n * PP + j] = g_lognu2[n * PP + j] - lse;
}

// ------------------------ iteration: u update ----------------------------
__global__ void __launch_bounds__(128) rowsweep_k() {
    const int n = blockIdx.y, ib = blockIdx.x;
    __shared__ float vs[PP];
    __shared__ float red[128];
    const int tid = threadIdx.x;

    float lmax = -1e30f;
    const float4* vp = (const float4*)(g_vK + n * PP);
    float4* vs4 = (float4*)vs;
#pragma unroll
    for (int k = tid; k < PP / 4; k += 128) {
        float4 v = vp[k];
        vs4[k] = v;
        lmax = fmaxf(lmax, fmaxf(fmaxf(v.x, v.y), fmaxf(v.z, v.w)));
    }
    red[tid] = lmax;
    __syncthreads();
#pragma unroll
    for (int st = 64; st; st >>= 1) {
        if (tid < st) red[tid] = fmaxf(red[tid], red[tid + st]);
        __syncthreads();
    }
    const float Bv = red[0];
#pragma unroll
    for (int k = tid; k < PP; k += 128) vs[k] -= Bv;
    __syncthreads();

    const int i = ib * 128 + tid;
    int cnt = g_rcnt[n * PP + i];
#pragma unroll
    for (int o = 16; o; o >>= 1) cnt = max(cnt, __shfl_xor_sync(0xFFFFFFFFu, cnt, o));

    const float* tp = g_rt + n * PP + i;
    const unsigned short* ip = g_ridx + n * PP + i;
    float s = 0.f;
#pragma unroll 4
    for (int e = 0; e < cnt; ++e) {
        float t  = tp[e * (NB * PP)];
        int idx  = ip[e * (NB * PP)];
        s += ex2f(vs[idx] + t);
    }
    float lse = Bv - g_rminK[n * PP + i] + lg2f(s);
    g_uK[n * PP + i] = g_logmu2[n * PP + i] - lse;
}

// ------------------------------- final -----------------------------------
__global__ void __launch_bounds__(256) finalpass(const float* __restrict__ C,
                                                 float* __restrict__ pi) {
    const int n = blockIdx.y, ib = blockIdx.x;
    __shared__ float vsK[PP];
    __shared__ float usr[16];
    __shared__ float red[256];
    const int tid = threadIdx.x;

    for (int j = tid; j < PP; j += 256) vsK[j] = g_vK[n * PP + j];
    if (tid < 16) usr[tid] = g_uK[n * PP + ib * 16 + tid];
    __syncthreads();

    const float4* Cb = (const float4*)(C + ((size_t)n << 20) + (size_t)ib * 16 * PP);
    float4* Pb = pi ? (float4*)(pi + ((size_t)n << 20) + (size_t)ib * 16 * PP) : nullptr;
    const float4* vs4 = (const float4*)vsK;

    float acc = 0.f;
#pragma unroll 4
    for (int e = tid; e < 4096; e += 256) {
        int row = e >> 8;
        int c4  = e & 255;
        float uK = usr[row];
        float4 c  = Cb[e];
        float4 vv = vs4[c4];
        float p0 = ex2f(fmaf(c.x, NKLOG, uK + vv.x));
        float p1 = ex2f(fmaf(c.y, NKLOG, uK + vv.y));
        float p2 = ex2f(fmaf(c.z, NKLOG, uK + vv.z));
        float p3 = ex2f(fmaf(c.w, NKLOG, uK + vv.w));
        acc = fmaf(p0, c.x, acc);
        acc = fmaf(p1, c.y, acc);
        acc = fmaf(p2, c.z, acc);
        acc = fmaf(p3, c.w, acc);
        if (Pb) Pb[e] = make_float4(p0, p1, p2, p3);
    }

    red[tid] = acc;
    __syncthreads();
#pragma unroll
    for (int st = 128; st; st >>= 1) {
        if (tid < st) red[tid] += red[tid + st];
        __syncthreads();
    }
    if (tid == 0) g_part[n * 64 + ib] = red[0];
}

__global__ void costred(float* __restrict__ cost) {
    int n = threadIdx.x;
    if (n < NB) {
        float s = 0.f;
#pragma unroll
        for (int k = 0; k < 64; ++k) s += g_part[n * 64 + k];
        if (cost) cost[n] = s;
        else      g_cost[n] = s;
    }
}

extern "C" void kernel_launch(void* const* d_in, const int* in_sizes, int n_in,
                              void* d_out, int out_size) {
    // C is the largest input; the remaining two are mu, nu in order.
    int ci = 0;
    for (int k = 1; k < n_in; ++k) if (in_sizes[k] > in_sizes[ci]) ci = k;
    const float* in2[2]; int w = 0;
    for (int k = 0; k < n_in && w < 2; ++k) if (k != ci) in2[w++] = (const float*)d_in[k];
    const float* mu = in2[0];
    const float* nu = in2[1];
    const float* C  = (const float*)d_in[ci];

    float* out = (float*)d_out;
    float* cost = nullptr;
    float* pi   = nullptr;
    const int NPI = NB * PP * PP;
    if (out_size >= NPI + NB)      { cost = out;     pi = out + NB; }
    else if (out_size == NPI)      { cost = nullptr; pi = out; }
    else                           { cost = out;     pi = nullptr; }

    init_k<<<(NB * PP + 255) / 256, 256>>>(mu, nu);
    colmin_k<<<dim3(16, 16), 256>>>(C);
    rowmin_k<<<dim3(16, 16), 256>>>(C);
    colcompact_k<<<dim3(4, 16), 256>>>(C);
    rowcompact_k<<<dim3(128, 16), 256>>>(C);

    for (int it = 0; it < 100; ++it) {
        colsweep_k<<<dim3(8, 16), 128>>>();
        rowsweep_k<<<dim3(8, 16), 128>>>();
    }

    finalpass<<<dim3(64, 16), 256>>>(C, pi);
    costred<<<1, 32>>>(cost);
}